// round 6
// baseline (speedup 1.0000x reference)
#include <cuda_runtime.h>
#include <math.h>
#include <stdint.h>

#define NB 64
#define CC 256
#define TT 64
#define VV 25
#define HID 16
#define CHUNK (TT*VV)          // 1600 floats per (n,c)

#define CH 32                  // chunks per block (resident in SMEM)
#define CS 8                   // cluster size: CS*CH = 256 = CC
#define THREADS 1024

// -------- dynamic SMEM layout (float offsets) --------
#define O_SX     0                       // CH*CHUNK = 51200 floats (200 KB)
#define O_PA     (O_SX + CH*CHUNK)       // 32
#define O_PM     (O_PA + CH)             // 32
#define O_PARTA  (O_PM + CH)             // 80 (5*16 partial, avg branch)
#define O_PARTM  (O_PARTA + 80)          // 80
#define O_SUMA   (O_PARTM + 80)          // 80
#define O_SUMM   (O_SUMA + 80)           // 80
#define O_HS     (O_SUMM + 80)           // 80
#define O_SG5    (O_HS + 80)             // 160 (gate per (f, cl))
#define O_SGATE  (O_SG5 + 160)           // CH*32 = 1024 (gate per (cl, joint))
#define O_LUT    (O_SGATE + CH*32)       // 64 ints (perm + grp)
#define SMEM_FLOATS (O_LUT + 64)
#define SMEM_BYTES  (SMEM_FLOATS * 4)    // 211,776 B < 227 KB

__constant__ int c_perm[VV] = {0,1,2,3,20,  8,9,10,11,23,24,  16,17,18,19,  4,5,6,7,21,22,  12,13,14,15};
__constant__ int c_grp[VV]  = {0,0,0,0,0,   1,1,1,1,1,1,      2,2,2,2,      3,3,3,3,3,3,    4,4,4,4};

__device__ __forceinline__ void cluster_sync() {
    asm volatile("barrier.cluster.arrive.aligned;" ::: "memory");
    asm volatile("barrier.cluster.wait.aligned;"   ::: "memory");
}
__device__ __forceinline__ float ld_dsmem_f32(uint32_t local_addr, uint32_t rank) {
    uint32_t remote; float v;
    asm("mapa.shared::cluster.u32 %0, %1, %2;" : "=r"(remote) : "r"(local_addr), "r"(rank));
    asm("ld.shared::cluster.f32 %0, [%1];" : "=f"(v) : "r"(remote));
    return v;
}

__global__ __launch_bounds__(THREADS, 1) __cluster_dims__(CS, 1, 1)
void fused_kernel(const float* __restrict__ x,
                  const float* __restrict__ W1, const float* __restrict__ b1,
                  const float* __restrict__ W2, const float* __restrict__ b2,
                  float* __restrict__ out) {
    extern __shared__ float sm[];
    int*   lut  = (int*)(sm + O_LUT);
    const int tid = threadIdx.x;
    uint32_t rk;  asm("mov.u32 %0, %%cluster_ctarank;" : "=r"(rk));
    const int n  = blockIdx.x >> 3;            // cluster id = batch index
    const int c0 = (int)rk * CH;               // first channel of this block
    const size_t gbase = ((size_t)n * CC + c0) * CHUNK;
    const uint32_t smem_u32 = (uint32_t)__cvta_generic_to_shared(sm);

    // ---- phase 1a: load CH chunks coalesced into SMEM ----
    const float4* __restrict__ src = reinterpret_cast<const float4*>(x + gbase);
    for (int idx = tid; idx < CH * CHUNK / 4; idx += THREADS)
        reinterpret_cast<float4*>(sm + O_SX)[idx] = src[idx];
    if (tid < VV) { lut[tid] = c_perm[tid]; lut[32 + tid] = c_grp[tid]; }
    __syncthreads();

    // ---- phase 1b: torso mean/max per chunk (warp w <-> chunk w) ----
    {
        const int w = tid >> 5, lane = tid & 31;
        float s = 0.f, m = -INFINITY;
#pragma unroll
        for (int half = 0; half < 2; half++) {
            const float* row = sm + O_SX + w * CHUNK + (lane + half * 32) * VV;
            float v0 = row[0], v1 = row[1], v2 = row[2], v3 = row[3], v4 = row[20];
            s += (v0 + v1) + (v2 + v3) + v4;
            m = fmaxf(m, fmaxf(fmaxf(v0, v1), fmaxf(fmaxf(v2, v3), v4)));
        }
#pragma unroll
        for (int o = 16; o; o >>= 1) {
            s += __shfl_xor_sync(0xffffffffu, s, o);
            m = fmaxf(m, __shfl_xor_sync(0xffffffffu, m, o));
        }
        if (lane == 0) { sm[O_PA + w] = s * (1.0f / 320.0f); sm[O_PM + w] = m; }
    }
    __syncthreads();

    // ---- phase 2a: partial W1·p over this block's 32 channels ----
    if (tid < 80) {                              // tid = f*16 + h
        const float* w1row = W1 + tid * CC + c0;
        float sa = 0.f, smm = 0.f;
#pragma unroll
        for (int cl = 0; cl < CH; cl++) {
            float w = w1row[cl];
            sa  = fmaf(w, sm[O_PA + cl], sa);
            smm = fmaf(w, sm[O_PM + cl], smm);
        }
        sm[O_PARTA + tid] = sa;
        sm[O_PARTM + tid] = smm;
    }
    cluster_sync();                              // partials visible cluster-wide

    // ---- phase 2b: sum partials across the 8 ranks (DSMEM reads) ----
    if (tid < 160) {
        const int which = tid >= 80;             // 0: avg, 1: max
        const int i = tid - which * 80;
        const uint32_t laddr = smem_u32 + (uint32_t)(((which ? O_PARTM : O_PARTA) + i) * 4);
        float v[CS];
#pragma unroll
        for (int r = 0; r < CS; r++) v[r] = ld_dsmem_f32(laddr, (uint32_t)r);
        float acc = ((v[0]+v[1])+(v[2]+v[3])) + ((v[4]+v[5])+(v[6]+v[7]));
        sm[(which ? O_SUMM : O_SUMA) + i] = acc;
    }
    cluster_sync();                              // everyone done reading remote part[]

    // ---- phase 2c: hidden = relu(a)+relu(m); gates for this block's channels ----
    if (tid < 80) {
        float b = b1[tid];
        sm[O_HS + tid] = fmaxf(sm[O_SUMA + tid] + b, 0.f) + fmaxf(sm[O_SUMM + tid] + b, 0.f);
    }
    __syncthreads();
    if (tid < 5 * CH) {                          // f = tid>>5, cl = tid&31
        const int f = tid >> 5, cl = tid & 31, c = c0 + cl;
        const float* w2row = W2 + ((size_t)f * CC + c) * HID;
        float o = 2.0f * b2[f * CC + c];
#pragma unroll
        for (int h = 0; h < HID; h++) o = fmaf(sm[O_HS + f * HID + h], w2row[h], o);
        sm[O_SG5 + f * CH + cl] = 1.0f / (1.0f + expf(-o));
    }
    __syncthreads();
    {                                            // sgate[cl*32+j] = sg5[grp[j]*32+cl]
        const int cl = tid >> 5, j = tid & 31;
        if (j < VV) sm[O_SGATE + tid] = sm[O_SG5 + lut[32 + j] * CH + cl];
    }
    __syncthreads();

    // ---- phase 3: permute + gate from SMEM, streaming float4 stores ----
    float4* __restrict__ dst = reinterpret_cast<float4*>(out + gbase);
    for (int idx = tid; idx < CH * CHUNK / 4; idx += THREADS) {
        int e0 = idx * 4;
        int cl = e0 / CHUNK;
        int rem = e0 - cl * CHUNK;
        float r[4];
#pragma unroll
        for (int k = 0; k < 4; k++) {
            int e = rem + k;
            int t = e / VV;
            int j = e - t * VV;
            r[k] = sm[O_SX + cl * CHUNK + t * VV + lut[j]] * sm[O_SGATE + cl * 32 + j];
        }
        __stcs(&dst[idx], make_float4(r[0], r[1], r[2], r[3]));
    }
    cluster_sync();                              // no CTA exits while cluster peers run
}

extern "C" void kernel_launch(void* const* d_in, const int* in_sizes, int n_in,
                              void* d_out, int out_size) {
    const float* x  = (const float*)d_in[0];
    const float* W1 = (const float*)d_in[1];
    const float* b1 = (const float*)d_in[2];
    const float* W2 = (const float*)d_in[3];
    const float* b2 = (const float*)d_in[4];
    float* out = (float*)d_out;

    cudaFuncSetAttribute(fused_kernel, cudaFuncAttributeMaxDynamicSharedMemorySize, SMEM_BYTES);
    fused_kernel<<<NB * CS, THREADS, SMEM_BYTES>>>(x, W1, b1, W2, b2, out);
}